// round 5
// baseline (speedup 1.0000x reference)
#include <cuda_runtime.h>
#include <cstdint>
#include <cstddef>

#define HID   256
#define NMSG  200001
#define MPAD  200064   // NMSG rounded up to multiple of 128
#define NTREE 512

// ---------------- scratch (device globals: no allocation allowed) ----------
__device__ float g_h   [(size_t)MPAD * HID];
__device__ float g_hUr [(size_t)MPAD * HID];
__device__ float g_r1  [(size_t)MPAD * HID];   // x@Wr + bUr
__device__ float g_xWz [(size_t)MPAD * HID];   // x@Wz_top + bz
__device__ float g_xWh [(size_t)MPAD * HID];   // x@Wh_top + bh
__device__ float g_sumh[(size_t)MPAD * HID];
__device__ float g_sg  [(size_t)MPAD * HID];

__device__ __forceinline__ float fsigmoid(float x) {
    return 1.0f / (1.0f + __expf(-x));
}
__device__ __forceinline__ float ftanh(float x) {
    x = fminf(fmaxf(x, -15.0f), 15.0f);
    float e = __expf(2.0f * x);
    return (e - 1.0f) / (e + 1.0f);
}
__device__ __forceinline__ uint32_t f2tf(float f) {
    uint32_t u;
    asm("cvt.rna.tf32.f32 %0, %1;" : "=r"(u) : "f"(f));
    return u;
}
__device__ __forceinline__ void mma8(float c[4], const uint32_t a[4], const uint32_t b[2]) {
    asm volatile(
        "mma.sync.aligned.m16n8k8.row.col.f32.tf32.tf32.f32 "
        "{%0,%1,%2,%3}, {%4,%5,%6,%7}, {%8,%9}, {%0,%1,%2,%3};"
        : "+f"(c[0]), "+f"(c[1]), "+f"(c[2]), "+f"(c[3])
        : "r"(a[0]), "r"(a[1]), "r"(a[2]), "r"(a[3]),
          "r"(b[0]), "r"(b[1]));
}

// k-permutation within a 32-wide chunk: position = (k&3)*8 + (k>>2)
// A float4 at [row][tig*8 + h*4] then holds (a0,a2) for k-steps 2h, 2h+1.
#define KPERM(k) (((k) & 3) * 8 + ((k) >> 2))
#define SPAD 36

// ---------------------------------------------------------------------------
// tf32 GEMM, shared A operand, NB outputs:
//   C_i[M x 256] = A[M x 256] @ B_i[256 x 256] (+ bias_i)
// GATHER: A row r = emb[fnode[fmess[r]]]
// BM=128, BN=64, BK=32, 256 threads (8 warps 4x2), warp tile 32x32.
// ---------------------------------------------------------------------------
template<int NB, bool GATHER>
__global__ void __launch_bounds__(256)
gemm_multiB(const float* __restrict__ A,
            const float* __restrict__ B0, const float* __restrict__ B1,
            const float* __restrict__ B2,
            const float* __restrict__ bias0, const float* __restrict__ bias1,
            const float* __restrict__ bias2,
            float* __restrict__ C0, float* __restrict__ C1,
            float* __restrict__ C2,
            const int* __restrict__ fmess, const int* __restrict__ fnode,
            const float* __restrict__ emb)
{
    __shared__ __align__(16) uint32_t As[128][SPAD];
    __shared__ __align__(16) uint32_t Bs[NB][64][SPAD];

    const int m0  = blockIdx.x * 128;
    const int n0  = blockIdx.y * 64;
    const int tid = threadIdx.x;
    const int lane = tid & 31, w = tid >> 5;
    const int wm = w >> 1, wn = w & 1;
    const int g  = lane >> 2, tig = lane & 3;

    const float* Bp[3] = {B0, B1, B2};

    const float* aptr[4];
    bool aval[4];
#pragma unroll
    for (int l = 0; l < 4; l++) {
        int idx = tid + l * 256;
        int r   = idx >> 3;
        int row = m0 + r;
        aval[l] = (row < NMSG);
        if (aval[l]) {
            if (GATHER) aptr[l] = emb + (size_t)fnode[fmess[row]] * HID;
            else        aptr[l] = A + (size_t)row * HID;
        } else {
            aptr[l] = GATHER ? emb : A;
        }
    }

    float acc[NB][2][4][4];
#pragma unroll
    for (int nb = 0; nb < NB; nb++)
#pragma unroll
        for (int mi = 0; mi < 2; mi++)
#pragma unroll
            for (int ni = 0; ni < 4; ni++)
#pragma unroll
                for (int q = 0; q < 4; q++) acc[nb][mi][ni][q] = 0.f;

    // register prefetch buffers
    float4 apre[4];
    float4 bpre[NB][2];
#pragma unroll
    for (int l = 0; l < 4; l++) {
        int idx = tid + l * 256;
        int k4  = (idx & 7) * 4;
        apre[l] = aval[l] ? *(const float4*)(aptr[l] + k4)
                          : make_float4(0.f, 0.f, 0.f, 0.f);
    }
#pragma unroll
    for (int nb = 0; nb < NB; nb++)
#pragma unroll
        for (int l = 0; l < 2; l++) {
            int idx = tid + l * 256;
            int r = idx >> 4, c4 = (idx & 15) * 4;
            bpre[nb][l] = *(const float4*)(Bp[nb] + (size_t)r * HID + n0 + c4);
        }

    for (int ck = 0; ck < 8; ck++) {
        __syncthreads();
        // stage current chunk (convert + permute)
#pragma unroll
        for (int l = 0; l < 4; l++) {
            int idx = tid + l * 256;
            int r = idx >> 3, k4 = (idx & 7) * 4;
            const float* v = (const float*)&apre[l];
#pragma unroll
            for (int j = 0; j < 4; j++) As[r][KPERM(k4 + j)] = f2tf(v[j]);
        }
#pragma unroll
        for (int nb = 0; nb < NB; nb++)
#pragma unroll
            for (int l = 0; l < 2; l++) {
                int idx = tid + l * 256;
                int r = idx >> 4, c4 = (idx & 15) * 4;
                const float* v = (const float*)&bpre[nb][l];
#pragma unroll
                for (int j = 0; j < 4; j++) Bs[nb][c4 + j][KPERM(r)] = f2tf(v[j]);
            }
        __syncthreads();
        // prefetch next chunk
        if (ck < 7) {
            int k0 = (ck + 1) * 32;
#pragma unroll
            for (int l = 0; l < 4; l++) {
                int idx = tid + l * 256;
                int k4  = (idx & 7) * 4;
                if (aval[l]) apre[l] = *(const float4*)(aptr[l] + k0 + k4);
            }
#pragma unroll
            for (int nb = 0; nb < NB; nb++)
#pragma unroll
                for (int l = 0; l < 2; l++) {
                    int idx = tid + l * 256;
                    int r = idx >> 4, c4 = (idx & 15) * 4;
                    bpre[nb][l] = *(const float4*)(Bp[nb] + (size_t)(k0 + r) * HID + n0 + c4);
                }
        }
        // compute on staged chunk
#pragma unroll
        for (int hh2 = 0; hh2 < 2; hh2++) {
            uint4 a4[2][2];
#pragma unroll
            for (int mi = 0; mi < 2; mi++) {
                int rb = wm * 32 + mi * 16 + g;
                a4[mi][0] = *(const uint4*)&As[rb    ][tig * 8 + hh2 * 4];
                a4[mi][1] = *(const uint4*)&As[rb + 8][tig * 8 + hh2 * 4];
            }
#pragma unroll
            for (int nb = 0; nb < NB; nb++) {
                uint4 b4[4];
#pragma unroll
                for (int ni = 0; ni < 4; ni++) {
                    int col = wn * 32 + ni * 8 + g;
                    b4[ni] = *(const uint4*)&Bs[nb][col][tig * 8 + hh2 * 4];
                }
#pragma unroll
                for (int j = 0; j < 2; j++)
#pragma unroll
                    for (int mi = 0; mi < 2; mi++)
#pragma unroll
                        for (int ni = 0; ni < 4; ni++) {
                            const uint32_t* au0 = (const uint32_t*)&a4[mi][0];
                            const uint32_t* au1 = (const uint32_t*)&a4[mi][1];
                            const uint32_t* bu  = (const uint32_t*)&b4[ni];
                            uint32_t aa[4] = {au0[2*j], au1[2*j], au0[2*j+1], au1[2*j+1]};
                            uint32_t bb[2] = {bu[2*j], bu[2*j+1]};
                            mma8(acc[nb][mi][ni], aa, bb);
                        }
            }
        }
    }

    // epilogue: bias add
    const float* biasp[3] = {bias0, bias1, bias2};
    float* Cp[3] = {C0, C1, C2};
#pragma unroll
    for (int nb = 0; nb < NB; nb++) {
#pragma unroll
        for (int ni = 0; ni < 4; ni++) {
            int col = n0 + wn * 32 + ni * 8 + tig * 2;
            float bvx = 0.f, bvy = 0.f;
            if (biasp[nb]) {
                float2 b2 = *(const float2*)(biasp[nb] + col);
                bvx = b2.x; bvy = b2.y;
            }
#pragma unroll
            for (int mi = 0; mi < 2; mi++)
#pragma unroll
                for (int hh = 0; hh < 2; hh++) {
                    int row = m0 + wm * 32 + mi * 16 + g + hh * 8;
                    if (row < NMSG) {
                        float2 o;
                        o.x = acc[nb][mi][ni][hh * 2 + 0] + bvx;
                        o.y = acc[nb][mi][ni][hh * 2 + 1] + bvy;
                        *(float2*)(Cp[nb] + (size_t)row * HID + col) = o;
                    }
                }
        }
    }
}

// ---------------------------------------------------------------------------
// Dual-A fused GRU GEMM (DYNAMIC shared memory, 55296 B):
//   acc0 = sum_h @ Uz ; acc1 = sg @ Uh
//   z = sigmoid(xWz + acc0); pre_h = tanh(xWh + acc1)
//   h = (1-z)*sum_h + z*pre_h   (row 0 -> 0)
// ---------------------------------------------------------------------------
#define GRU_SMEM_WORDS ((2 * 128 + 2 * 64) * SPAD)
#define GRU_SMEM_BYTES (GRU_SMEM_WORDS * 4)

__global__ void __launch_bounds__(256)
gemm_gru(const float* __restrict__ A0,   // sum_h
         const float* __restrict__ A1,   // sg
         const float* __restrict__ Buz, const float* __restrict__ Buh,
         const float* __restrict__ xWz, const float* __restrict__ xWh,
         float* __restrict__ Cout)
{
    extern __shared__ __align__(16) uint32_t smemraw[];
    // As: 2 x 128 rows of SPAD, Bs: 2 x 64 rows of SPAD (after As)
    uint32_t (*As)[SPAD] = (uint32_t(*)[SPAD])smemraw;
    uint32_t (*Bs)[SPAD] = (uint32_t(*)[SPAD])(smemraw + 2 * 128 * SPAD);

    const int m0  = blockIdx.x * 128;
    const int n0  = blockIdx.y * 64;
    const int tid = threadIdx.x;
    const int lane = tid & 31, w = tid >> 5;
    const int wm = w >> 1, wn = w & 1;
    const int g  = lane >> 2, tig = lane & 3;

    const float* Ap[2] = {A0, A1};
    const float* Bp[2] = {Buz, Buh};

    bool aval[4];
    size_t aoff[4];
#pragma unroll
    for (int l = 0; l < 4; l++) {
        int idx = tid + l * 256;
        int r   = idx >> 3;
        int row = m0 + r;
        aval[l] = (row < NMSG);
        aoff[l] = (size_t)(aval[l] ? row : 0) * HID + (idx & 7) * 4;
    }

    float acc[2][2][4][4];
#pragma unroll
    for (int o = 0; o < 2; o++)
#pragma unroll
        for (int mi = 0; mi < 2; mi++)
#pragma unroll
            for (int ni = 0; ni < 4; ni++)
#pragma unroll
                for (int q = 0; q < 4; q++) acc[o][mi][ni][q] = 0.f;

    float4 apre[2][4];
    float4 bpre[2][2];
#pragma unroll
    for (int o = 0; o < 2; o++) {
#pragma unroll
        for (int l = 0; l < 4; l++)
            apre[o][l] = aval[l] ? *(const float4*)(Ap[o] + aoff[l])
                                 : make_float4(0.f, 0.f, 0.f, 0.f);
#pragma unroll
        for (int l = 0; l < 2; l++) {
            int idx = tid + l * 256;
            int r = idx >> 4, c4 = (idx & 15) * 4;
            bpre[o][l] = *(const float4*)(Bp[o] + (size_t)r * HID + n0 + c4);
        }
    }

    for (int ck = 0; ck < 8; ck++) {
        __syncthreads();
#pragma unroll
        for (int o = 0; o < 2; o++) {
#pragma unroll
            for (int l = 0; l < 4; l++) {
                int idx = tid + l * 256;
                int r = idx >> 3, k4 = (idx & 7) * 4;
                const float* v = (const float*)&apre[o][l];
#pragma unroll
                for (int j = 0; j < 4; j++) As[o * 128 + r][KPERM(k4 + j)] = f2tf(v[j]);
            }
#pragma unroll
            for (int l = 0; l < 2; l++) {
                int idx = tid + l * 256;
                int r = idx >> 4, c4 = (idx & 15) * 4;
                const float* v = (const float*)&bpre[o][l];
#pragma unroll
                for (int j = 0; j < 4; j++) Bs[o * 64 + c4 + j][KPERM(r)] = f2tf(v[j]);
            }
        }
        __syncthreads();
        if (ck < 7) {
            int k0 = (ck + 1) * 32;
#pragma unroll
            for (int o = 0; o < 2; o++) {
#pragma unroll
                for (int l = 0; l < 4; l++)
                    if (aval[l]) apre[o][l] = *(const float4*)(Ap[o] + aoff[l] + k0);
#pragma unroll
                for (int l = 0; l < 2; l++) {
                    int idx = tid + l * 256;
                    int r = idx >> 4, c4 = (idx & 15) * 4;
                    bpre[o][l] = *(const float4*)(Bp[o] + (size_t)(k0 + r) * HID + n0 + c4);
                }
            }
        }
#pragma unroll
        for (int hh2 = 0; hh2 < 2; hh2++) {
#pragma unroll
            for (int o = 0; o < 2; o++) {
                uint4 a4[2][2];
#pragma unroll
                for (int mi = 0; mi < 2; mi++) {
                    int rb = o * 128 + wm * 32 + mi * 16 + g;
                    a4[mi][0] = *(const uint4*)&As[rb    ][tig * 8 + hh2 * 4];
                    a4[mi][1] = *(const uint4*)&As[rb + 8][tig * 8 + hh2 * 4];
                }
                uint4 b4[4];
#pragma unroll
                for (int ni = 0; ni < 4; ni++) {
                    int col = o * 64 + wn * 32 + ni * 8 + g;
                    b4[ni] = *(const uint4*)&Bs[col][tig * 8 + hh2 * 4];
                }
#pragma unroll
                for (int j = 0; j < 2; j++)
#pragma unroll
                    for (int mi = 0; mi < 2; mi++)
#pragma unroll
                        for (int ni = 0; ni < 4; ni++) {
                            const uint32_t* au0 = (const uint32_t*)&a4[mi][0];
                            const uint32_t* au1 = (const uint32_t*)&a4[mi][1];
                            const uint32_t* bu  = (const uint32_t*)&b4[ni];
                            uint32_t aa[4] = {au0[2*j], au1[2*j], au0[2*j+1], au1[2*j+1]};
                            uint32_t bb[2] = {bu[2*j], bu[2*j+1]};
                            mma8(acc[o][mi][ni], aa, bb);
                        }
            }
        }
    }

    // fused GRU epilogue
#pragma unroll
    for (int ni = 0; ni < 4; ni++) {
        int col = n0 + wn * 32 + ni * 8 + tig * 2;
#pragma unroll
        for (int mi = 0; mi < 2; mi++)
#pragma unroll
            for (int hh = 0; hh < 2; hh++) {
                int row = m0 + wm * 32 + mi * 16 + g + hh * 8;
                if (row < NMSG) {
                    size_t off = (size_t)row * HID + col;
                    float2 wz = *(const float2*)(xWz + off);
                    float2 wh = *(const float2*)(xWh + off);
                    float2 sh = *(const float2*)(A0  + off);
                    float2 o;
                    {
                        float z = fsigmoid(wz.x + acc[0][mi][ni][hh * 2 + 0]);
                        float p = ftanh(wh.x + acc[1][mi][ni][hh * 2 + 0]);
                        o.x = (1.f - z) * sh.x + z * p;
                    }
                    {
                        float z = fsigmoid(wz.y + acc[0][mi][ni][hh * 2 + 1]);
                        float p = ftanh(wh.y + acc[1][mi][ni][hh * 2 + 1]);
                        o.y = (1.f - z) * sh.y + z * p;
                    }
                    if (row == 0) { o.x = 0.f; o.y = 0.f; }
                    *(float2*)(Cout + off) = o;
                }
            }
    }
}

// ---------------------------------------------------------------------------
// Gather: per message m:
//   sum_h[m] = sum_d h[n_d]
//   sg[m]    = sum_d sigmoid(r1[m] + hUr[n_d]) * h[n_d]
// ---------------------------------------------------------------------------
__global__ void __launch_bounds__(256)
gather_kernel(const float* __restrict__ h,
              const float* __restrict__ hUr,
              const float* __restrict__ r1,
              const int* __restrict__ mess_graph,
              float* __restrict__ sumh,
              float* __restrict__ sg)
{
    int m = blockIdx.x * 4 + (threadIdx.x >> 6);
    if (m >= NMSG) return;
    int cc = (threadIdx.x & 63) * 4;

    int4 nb = *(const int4*)(mess_graph + (size_t)m * 4);
    int n[4] = {nb.x, nb.y, nb.z, nb.w};

    size_t moff = (size_t)m * HID + cc;
    float4 r1v = *(const float4*)(r1 + moff);
    float4 s = make_float4(0.f, 0.f, 0.f, 0.f);
    float4 gg = make_float4(0.f, 0.f, 0.f, 0.f);

#pragma unroll
    for (int d = 0; d < 4; d++) {
        size_t off = (size_t)n[d] * HID + cc;
        float4 hv = *(const float4*)(h   + off);
        float4 rv = *(const float4*)(hUr + off);
        float r;
        r = fsigmoid(r1v.x + rv.x); s.x += hv.x; gg.x += r * hv.x;
        r = fsigmoid(r1v.y + rv.y); s.y += hv.y; gg.y += r * hv.y;
        r = fsigmoid(r1v.z + rv.z); s.z += hv.z; gg.z += r * hv.z;
        r = fsigmoid(r1v.w + rv.w); s.w += hv.w; gg.w += r * hv.w;
    }
    *(float4*)(sumh + moff) = s;
    *(float4*)(sg   + moff) = gg;
}

// ---------------------------------------------------------------------------
// Iteration 1 (h=0 shortcut): h = sigmoid(xWz) * tanh(xWh), row 0 -> 0
// ---------------------------------------------------------------------------
__global__ void __launch_bounds__(256)
iter1_kernel(const float* __restrict__ xWz,
             const float* __restrict__ xWh,
             float* __restrict__ h)
{
    size_t idx = (size_t)blockIdx.x * 256 + threadIdx.x;
    const size_t total = (size_t)NMSG * (HID / 4);
    if (idx >= total) return;
    size_t off = idx * 4;
    float4 a = *(const float4*)(xWz + off);
    float4 b = *(const float4*)(xWh + off);
    float4 o;
    o.x = fsigmoid(a.x) * ftanh(b.x);
    o.y = fsigmoid(a.y) * ftanh(b.y);
    o.z = fsigmoid(a.z) * ftanh(b.z);
    o.w = fsigmoid(a.w) * ftanh(b.w);
    if (idx < (HID / 4)) o = make_float4(0.f, 0.f, 0.f, 0.f);
    *(float4*)(h + off) = o;
}

// ---------------------------------------------------------------------------
// Epilogue: only the 512 roots matter.
// ---------------------------------------------------------------------------
__global__ void __launch_bounds__(256)
epilogue_kernel(const int* __restrict__ root_indices,
                const int* __restrict__ fnode,
                const int* __restrict__ node_graph,
                const float* __restrict__ emb,
                const float* __restrict__ messages,
                const float* __restrict__ Wo,
                const float* __restrict__ bo,
                float* __restrict__ out)
{
    __shared__ float v[2 * HID];
    int b = blockIdx.x;
    int t = threadIdx.x;
    int node = root_indices[b];
    v[t] = emb[(size_t)fnode[node] * HID + t];
    float s = 0.f;
#pragma unroll
    for (int d = 0; d < 4; d++)
        s += messages[(size_t)node_graph[(size_t)node * 4 + d] * HID + t];
    v[HID + t] = s;
    __syncthreads();

    float acc = bo[t];
#pragma unroll 4
    for (int k = 0; k < 2 * HID; k++)
        acc += v[k] * Wo[(size_t)k * HID + t];
    out[(size_t)b * HID + t] = fmaxf(acc, 0.f);
}

// ---------------------------------------------------------------------------
extern "C" void kernel_launch(void* const* d_in, const int* in_sizes, int n_in,
                              void* d_out, int out_size)
{
    const int*   fnode        = (const int*)  d_in[0];
    const int*   fmess        = (const int*)  d_in[1];
    const int*   node_graph   = (const int*)  d_in[2];
    const int*   mess_graph   = (const int*)  d_in[3];
    const int*   root_indices = (const int*)  d_in[4];
    const float* emb          = (const float*)d_in[5];
    const float* Wz           = (const float*)d_in[6];
    const float* bz           = (const float*)d_in[7];
    const float* Wr           = (const float*)d_in[8];
    const float* Ur           = (const float*)d_in[9];
    const float* bUr          = (const float*)d_in[10];
    const float* Wh           = (const float*)d_in[11];
    const float* bh           = (const float*)d_in[12];
    const float* Wo           = (const float*)d_in[13];
    const float* bo           = (const float*)d_in[14];

    float* out       = (float*)d_out;
    float* tree_vecs = out;                          // [512, 256]
    float* messages  = out + (size_t)NTREE * HID;    // [200001, 256]

    float *h, *hUr, *r1, *xWz, *xWh, *sumh, *sg;
    cudaGetSymbolAddress((void**)&h,    g_h);
    cudaGetSymbolAddress((void**)&hUr,  g_hUr);
    cudaGetSymbolAddress((void**)&r1,   g_r1);
    cudaGetSymbolAddress((void**)&xWz,  g_xWz);
    cudaGetSymbolAddress((void**)&xWh,  g_xWh);
    cudaGetSymbolAddress((void**)&sumh, g_sumh);
    cudaGetSymbolAddress((void**)&sg,   g_sg);

    // opt-in to >48KB dynamic smem for gemm_gru (host config, capture-safe)
    cudaFuncSetAttribute(gemm_gru,
                         cudaFuncAttributeMaxDynamicSharedMemorySize,
                         GRU_SMEM_BYTES);

    const float* Uz = Wz + (size_t)HID * HID;   // rows 256..511 of Wz
    const float* Uh = Wh + (size_t)HID * HID;   // rows 256..511 of Wh

    dim3 ggrid(MPAD / 128, HID / 64);
    const int nblk_msg = (NMSG + 3) / 4;

    // Prologue: r1 = x@Wr + bUr; xWz = x@Wz_top + bz; xWh = x@Wh_top + bh
    // with x = emb[fnode[fmess]] (never materialized)
    gemm_multiB<3, true><<<ggrid, 256>>>(
        nullptr, Wr, Wz, Wh, bUr, bz, bh, r1, xWz, xWh, fmess, fnode, emb);

    // GRU iteration 1 (h = 0): pure elementwise
    iter1_kernel<<<nblk_msg, 256>>>(xWz, xWh, h);

    // GRU iterations 2..10
    for (int t = 2; t <= 10; t++) {
        gemm_multiB<1, false><<<ggrid, 256>>>(
            h, Ur, nullptr, nullptr, nullptr, nullptr, nullptr,
            hUr, nullptr, nullptr, nullptr, nullptr, nullptr);
        gather_kernel<<<nblk_msg, 256>>>(h, hUr, r1, mess_graph, sumh, sg);
        float* hout = (t == 10) ? messages : h;
        gemm_gru<<<ggrid, 256, GRU_SMEM_BYTES>>>(sumh, sg, Uz, Uh, xWz, xWh, hout);
    }

    // Tree vectors from roots only
    epilogue_kernel<<<NTREE, 256>>>(root_indices, fnode, node_graph,
                                    emb, messages, Wo, bo, tree_vecs);

    (void)in_sizes; (void)n_in; (void)out_size;
}

// round 8
// speedup vs baseline: 1.0368x; 1.0368x over previous
#include <cuda_runtime.h>
#include <cstdint>
#include <cstddef>

#define HID   256
#define NMSG  200001
#define MPAD  200064   // NMSG rounded up to multiple of 128
#define NTREE 512
#define HCAT  768      // interleaved h | hUr | hUz row stride

// ---------------- scratch (device globals: no allocation allowed) ----------
__device__ float g_hcat[(size_t)MPAD * HCAT];  // [m][0:256)=h [256:512)=hUr [512:768)=hUz
__device__ float g_r1  [(size_t)MPAD * HID];   // x@Wr + bUr
__device__ float g_xWz [(size_t)MPAD * HID];   // x@Wz_top + bz
__device__ float g_xWh [(size_t)MPAD * HID];   // x@Wh_top + bh
__device__ float g_sg  [(size_t)MPAD * HID];   // sum(r * h_nei)
__device__ float g_a   [(size_t)MPAD * HID];   // (1-z) * sum_h
__device__ float g_z   [(size_t)MPAD * HID];   // z gate

__device__ __forceinline__ float fsigmoid(float x) {
    return 1.0f / (1.0f + __expf(-x));
}
__device__ __forceinline__ float ftanh(float x) {
    x = fminf(fmaxf(x, -15.0f), 15.0f);
    float e = __expf(2.0f * x);
    return (e - 1.0f) / (e + 1.0f);
}
__device__ __forceinline__ uint32_t f2tf(float f) {
    uint32_t u;
    asm("cvt.rna.tf32.f32 %0, %1;" : "=r"(u) : "f"(f));
    return u;
}
__device__ __forceinline__ void mma8(float c[4], const uint32_t a[4], const uint32_t b[2]) {
    asm volatile(
        "mma.sync.aligned.m16n8k8.row.col.f32.tf32.tf32.f32 "
        "{%0,%1,%2,%3}, {%4,%5,%6,%7}, {%8,%9}, {%0,%1,%2,%3};"
        : "+f"(c[0]), "+f"(c[1]), "+f"(c[2]), "+f"(c[3])
        : "r"(a[0]), "r"(a[1]), "r"(a[2]), "r"(a[3]),
          "r"(b[0]), "r"(b[1]));
}

// k-permutation within a 32-wide chunk: position = (k&3)*8 + (k>>2)
#define KPERM(k) (((k) & 3) * 8 + ((k) >> 2))
#define SPAD 36
// dynamic smem: 2 stages of (A 128 rows + B 64 rows) x SPAD words
#define G1_SMEM_BYTES (2 * (128 + 64) * SPAD * 4)

// ---------------------------------------------------------------------------
// tf32 GEMM, single B, double-buffered smem, ONE barrier per k-chunk.
//   C[M x 256] = A[M x 256] @ B[256 x 256] (+ bias)
// GATHER: A row r = emb[fnode[fmess[r]]]
// FUSE:   C = ea + ez * tanh(exWh + acc), row 0 -> 0  (GRU blend epilogue)
// BM=128, BN=64, BK=32, 256 threads (8 warps 4x2), warp tile 32x32.
// A rows use stride lda; C rows use stride ldc (for interleaved hcat).
// ---------------------------------------------------------------------------
template<bool GATHER, bool FUSE>
__global__ void __launch_bounds__(256)
gemm1(const float* __restrict__ A, int lda,
      const float* __restrict__ B,
      const float* __restrict__ bias,
      float* __restrict__ C, int ldc,
      const int* __restrict__ fmess, const int* __restrict__ fnode,
      const float* __restrict__ emb,
      const float* __restrict__ ea, const float* __restrict__ ez,
      const float* __restrict__ exWh)
{
    extern __shared__ __align__(16) uint32_t smemraw[];
    uint32_t* Asb = smemraw;                       // [2][128][SPAD]
    uint32_t* Bsb = smemraw + 2 * 128 * SPAD;      // [2][64][SPAD]

    const int m0  = blockIdx.x * 128;
    const int n0  = blockIdx.y * 64;
    const int tid = threadIdx.x;
    const int lane = tid & 31, w = tid >> 5;
    const int wm = w >> 1, wn = w & 1;
    const int g  = lane >> 2, tig = lane & 3;

    // A row pointers (fixed across k chunks)
    const float* aptr[4];
    bool aval[4];
#pragma unroll
    for (int l = 0; l < 4; l++) {
        int idx = tid + l * 256;
        int r   = idx >> 3;
        int row = m0 + r;
        aval[l] = (row < NMSG);
        if (aval[l]) {
            if (GATHER) aptr[l] = emb + (size_t)fnode[fmess[row]] * HID;
            else        aptr[l] = A + (size_t)row * lda;
        } else {
            aptr[l] = GATHER ? emb : A;
        }
    }

    float acc[2][4][4];
#pragma unroll
    for (int mi = 0; mi < 2; mi++)
#pragma unroll
        for (int ni = 0; ni < 4; ni++)
#pragma unroll
            for (int q = 0; q < 4; q++) acc[mi][ni][q] = 0.f;

    // ---- prefetch chunk 0 into registers ----
    float4 apre[4];
    float4 bpre[2];
#pragma unroll
    for (int l = 0; l < 4; l++) {
        int idx = tid + l * 256;
        int k4  = (idx & 7) * 4;
        apre[l] = aval[l] ? *(const float4*)(aptr[l] + k4)
                          : make_float4(0.f, 0.f, 0.f, 0.f);
    }
#pragma unroll
    for (int l = 0; l < 2; l++) {
        int idx = tid + l * 256;
        int r = idx >> 4, c4 = (idx & 15) * 4;
        bpre[l] = *(const float4*)(B + (size_t)r * HID + n0 + c4);
    }
    // ---- stage chunk 0 into buffer 0 ----
#pragma unroll
    for (int l = 0; l < 4; l++) {
        int idx = tid + l * 256;
        int r = idx >> 3, k4 = (idx & 7) * 4;
        const float* v = (const float*)&apre[l];
#pragma unroll
        for (int j = 0; j < 4; j++) Asb[r * SPAD + KPERM(k4 + j)] = f2tf(v[j]);
    }
#pragma unroll
    for (int l = 0; l < 2; l++) {
        int idx = tid + l * 256;
        int r = idx >> 4, c4 = (idx & 15) * 4;
        const float* v = (const float*)&bpre[l];
#pragma unroll
        for (int j = 0; j < 4; j++) Bsb[(c4 + j) * SPAD + KPERM(r)] = f2tf(v[j]);
    }
    __syncthreads();

    for (int ck = 0; ck < 8; ck++) {
        const int s = ck & 1;
        // issue LDGs for next chunk BEFORE compute (overlap with mma)
        if (ck < 7) {
            int k0 = (ck + 1) * 32;
#pragma unroll
            for (int l = 0; l < 4; l++) {
                int idx = tid + l * 256;
                int k4  = (idx & 7) * 4;
                if (aval[l]) apre[l] = *(const float4*)(aptr[l] + k0 + k4);
            }
#pragma unroll
            for (int l = 0; l < 2; l++) {
                int idx = tid + l * 256;
                int r = idx >> 4, c4 = (idx & 15) * 4;
                bpre[l] = *(const float4*)(B + (size_t)(k0 + r) * HID + n0 + c4);
            }
        }
        // compute from stage s
#pragma unroll
        for (int hh2 = 0; hh2 < 2; hh2++) {
            uint4 a4[2][2];
#pragma unroll
            for (int mi = 0; mi < 2; mi++) {
                int rb = wm * 32 + mi * 16 + g;
                a4[mi][0] = *(const uint4*)&Asb[(s * 128 + rb    ) * SPAD + tig * 8 + hh2 * 4];
                a4[mi][1] = *(const uint4*)&Asb[(s * 128 + rb + 8) * SPAD + tig * 8 + hh2 * 4];
            }
            uint4 b4[4];
#pragma unroll
            for (int ni = 0; ni < 4; ni++) {
                int col = wn * 32 + ni * 8 + g;
                b4[ni] = *(const uint4*)&Bsb[(s * 64 + col) * SPAD + tig * 8 + hh2 * 4];
            }
#pragma unroll
            for (int j = 0; j < 2; j++)
#pragma unroll
                for (int mi = 0; mi < 2; mi++)
#pragma unroll
                    for (int ni = 0; ni < 4; ni++) {
                        const uint32_t* au0 = (const uint32_t*)&a4[mi][0];
                        const uint32_t* au1 = (const uint32_t*)&a4[mi][1];
                        const uint32_t* bu  = (const uint32_t*)&b4[ni];
                        uint32_t aa[4] = {au0[2*j], au1[2*j], au0[2*j+1], au1[2*j+1]};
                        uint32_t bb[2] = {bu[2*j], bu[2*j+1]};
                        mma8(acc[mi][ni], aa, bb);
                    }
        }
        // stage next chunk into the alternate buffer (after compute; no WAR)
        if (ck < 7) {
            const int t = s ^ 1;
#pragma unroll
            for (int l = 0; l < 4; l++) {
                int idx = tid + l * 256;
                int r = idx >> 3, k4 = (idx & 7) * 4;
                const float* v = (const float*)&apre[l];
#pragma unroll
                for (int j = 0; j < 4; j++)
                    Asb[(t * 128 + r) * SPAD + KPERM(k4 + j)] = f2tf(v[j]);
            }
#pragma unroll
            for (int l = 0; l < 2; l++) {
                int idx = tid + l * 256;
                int r = idx >> 4, c4 = (idx & 15) * 4;
                const float* v = (const float*)&bpre[l];
#pragma unroll
                for (int j = 0; j < 4; j++)
                    Bsb[(t * 64 + c4 + j) * SPAD + KPERM(r)] = f2tf(v[j]);
            }
        }
        __syncthreads();
    }

    // epilogue
#pragma unroll
    for (int ni = 0; ni < 4; ni++) {
        int col = n0 + wn * 32 + ni * 8 + tig * 2;
        float bvx = 0.f, bvy = 0.f;
        if (!FUSE && bias) {
            float2 b2 = *(const float2*)(bias + col);
            bvx = b2.x; bvy = b2.y;
        }
#pragma unroll
        for (int mi = 0; mi < 2; mi++)
#pragma unroll
            for (int hh = 0; hh < 2; hh++) {
                int row = m0 + wm * 32 + mi * 16 + g + hh * 8;
                if (row < NMSG) {
                    float v0 = acc[mi][ni][hh * 2 + 0];
                    float v1 = acc[mi][ni][hh * 2 + 1];
                    float2 o;
                    if (FUSE) {
                        size_t eoff = (size_t)row * HID + col;
                        float2 av = *(const float2*)(ea   + eoff);
                        float2 zv = *(const float2*)(ez   + eoff);
                        float2 wv = *(const float2*)(exWh + eoff);
                        o.x = av.x + zv.x * ftanh(wv.x + v0);
                        o.y = av.y + zv.y * ftanh(wv.y + v1);
                        if (row == 0) { o.x = 0.f; o.y = 0.f; }
                    } else {
                        o.x = v0 + bvx;
                        o.y = v1 + bvy;
                    }
                    *(float2*)(C + (size_t)row * ldc + col) = o;
                }
            }
    }
}

// ---------------------------------------------------------------------------
// Gather over interleaved hcat. Per message m (neighbors n_d = mess_graph[m]):
//   sum_h = sum_d h[n_d];  u = sum_d hUz[n_d]
//   sg    = sum_d sigmoid(r1[m] + hUr[n_d]) * h[n_d]
//   z     = sigmoid(xWz[m] + u);  a = (1-z)*sum_h
// each neighbor read is one contiguous 3KB run (h|hUr|hUz interleaved).
// ---------------------------------------------------------------------------
__global__ void __launch_bounds__(256)
gather3(const float* __restrict__ hcat,
        const float* __restrict__ r1,
        const float* __restrict__ xWz,
        const int* __restrict__ mess_graph,
        float* __restrict__ sg,
        float* __restrict__ aout,
        float* __restrict__ zout)
{
    int m = blockIdx.x * 4 + (threadIdx.x >> 6);
    if (m >= NMSG) return;
    int cc = (threadIdx.x & 63) * 4;

    int4 nb = *(const int4*)(mess_graph + (size_t)m * 4);
    int n[4] = {nb.x, nb.y, nb.z, nb.w};

    size_t moff = (size_t)m * HID + cc;
    float4 r1v = *(const float4*)(r1 + moff);
    float4 s = make_float4(0.f, 0.f, 0.f, 0.f);
    float4 gg = make_float4(0.f, 0.f, 0.f, 0.f);
    float4 u = make_float4(0.f, 0.f, 0.f, 0.f);

#pragma unroll
    for (int d = 0; d < 4; d++) {
        const float* base = hcat + (size_t)n[d] * HCAT + cc;
        float4 hv = *(const float4*)(base);
        float4 rv = *(const float4*)(base + 256);
        float4 zv = *(const float4*)(base + 512);
        float r;
        r = fsigmoid(r1v.x + rv.x); s.x += hv.x; gg.x += r * hv.x; u.x += zv.x;
        r = fsigmoid(r1v.y + rv.y); s.y += hv.y; gg.y += r * hv.y; u.y += zv.y;
        r = fsigmoid(r1v.z + rv.z); s.z += hv.z; gg.z += r * hv.z; u.z += zv.z;
        r = fsigmoid(r1v.w + rv.w); s.w += hv.w; gg.w += r * hv.w; u.w += zv.w;
    }
    float4 xz = *(const float4*)(xWz + moff);
    float4 z;
    z.x = fsigmoid(xz.x + u.x);
    z.y = fsigmoid(xz.y + u.y);
    z.z = fsigmoid(xz.z + u.z);
    z.w = fsigmoid(xz.w + u.w);

    *(float4*)(sg + moff) = gg;
    float4 av;
    av.x = (1.f - z.x) * s.x; av.y = (1.f - z.y) * s.y;
    av.z = (1.f - z.z) * s.z; av.w = (1.f - z.w) * s.w;
    *(float4*)(aout + moff) = av;
    *(float4*)(zout + moff) = z;
}

// ---------------------------------------------------------------------------
// Iteration 1 (h=0 shortcut): h = sigmoid(xWz)*tanh(xWh) -> hcat slot 0
// ---------------------------------------------------------------------------
__global__ void __launch_bounds__(256)
iter1_kernel(const float* __restrict__ xWz,
             const float* __restrict__ xWh,
             float* __restrict__ hcat)
{
    size_t idx = (size_t)blockIdx.x * 256 + threadIdx.x;  // float4 index
    const size_t total = (size_t)NMSG * (HID / 4);
    if (idx >= total) return;
    size_t row = idx / (HID / 4);
    size_t c4  = (idx % (HID / 4)) * 4;
    float4 a = *(const float4*)(xWz + row * HID + c4);
    float4 b = *(const float4*)(xWh + row * HID + c4);
    float4 o;
    o.x = fsigmoid(a.x) * ftanh(b.x);
    o.y = fsigmoid(a.y) * ftanh(b.y);
    o.z = fsigmoid(a.z) * ftanh(b.z);
    o.w = fsigmoid(a.w) * ftanh(b.w);
    if (row == 0) o = make_float4(0.f, 0.f, 0.f, 0.f);
    *(float4*)(hcat + row * HCAT + c4) = o;
}

// ---------------------------------------------------------------------------
// Epilogue: only the 512 roots matter. messages has HID row stride.
// ---------------------------------------------------------------------------
__global__ void __launch_bounds__(256)
epilogue_kernel(const int* __restrict__ root_indices,
                const int* __restrict__ fnode,
                const int* __restrict__ node_graph,
                const float* __restrict__ emb,
                const float* __restrict__ messages,
                const float* __restrict__ Wo,
                const float* __restrict__ bo,
                float* __restrict__ out)
{
    __shared__ float v[2 * HID];
    int b = blockIdx.x;
    int t = threadIdx.x;
    int node = root_indices[b];
    v[t] = emb[(size_t)fnode[node] * HID + t];
    float s = 0.f;
#pragma unroll
    for (int d = 0; d < 4; d++)
        s += messages[(size_t)node_graph[(size_t)node * 4 + d] * HID + t];
    v[HID + t] = s;
    __syncthreads();

    float acc = bo[t];
#pragma unroll 4
    for (int k = 0; k < 2 * HID; k++)
        acc += v[k] * Wo[(size_t)k * HID + t];
    out[(size_t)b * HID + t] = fmaxf(acc, 0.f);
}

// ---------------------------------------------------------------------------
extern "C" void kernel_launch(void* const* d_in, const int* in_sizes, int n_in,
                              void* d_out, int out_size)
{
    const int*   fnode        = (const int*)  d_in[0];
    const int*   fmess        = (const int*)  d_in[1];
    const int*   node_graph   = (const int*)  d_in[2];
    const int*   mess_graph   = (const int*)  d_in[3];
    const int*   root_indices = (const int*)  d_in[4];
    const float* emb          = (const float*)d_in[5];
    const float* Wz           = (const float*)d_in[6];
    const float* bz           = (const float*)d_in[7];
    const float* Wr           = (const float*)d_in[8];
    const float* Ur           = (const float*)d_in[9];
    const float* bUr          = (const float*)d_in[10];
    const float* Wh           = (const float*)d_in[11];
    const float* bh           = (const float*)d_in[12];
    const float* Wo           = (const float*)d_in[13];
    const float* bo           = (const float*)d_in[14];

    float* out       = (float*)d_out;
    float* tree_vecs = out;                          // [512, 256]
    float* messages  = out + (size_t)NTREE * HID;    // [200001, 256]

    float *hcat, *r1, *xWz, *xWh, *sg, *a, *z;
    cudaGetSymbolAddress((void**)&hcat, g_hcat);
    cudaGetSymbolAddress((void**)&r1,   g_r1);
    cudaGetSymbolAddress((void**)&xWz,  g_xWz);
    cudaGetSymbolAddress((void**)&xWh,  g_xWh);
    cudaGetSymbolAddress((void**)&sg,   g_sg);
    cudaGetSymbolAddress((void**)&a,    g_a);
    cudaGetSymbolAddress((void**)&z,    g_z);

    // opt-in to >48KB dynamic smem (host-side config, capture-safe)
    cudaFuncSetAttribute(gemm1<true,  false>,
                         cudaFuncAttributeMaxDynamicSharedMemorySize, G1_SMEM_BYTES);
    cudaFuncSetAttribute(gemm1<false, false>,
                         cudaFuncAttributeMaxDynamicSharedMemorySize, G1_SMEM_BYTES);
    cudaFuncSetAttribute(gemm1<false, true>,
                         cudaFuncAttributeMaxDynamicSharedMemorySize, G1_SMEM_BYTES);

    const float* Uz = Wz + (size_t)HID * HID;   // rows 256..511 of Wz
    const float* Uh = Wh + (size_t)HID * HID;   // rows 256..511 of Wh

    dim3 ggrid(MPAD / 128, HID / 64);
    const int nblk_msg = (NMSG + 3) / 4;

    // Prologue: r1 = x@Wr + bUr; xWz = x@Wz_top + bz; xWh = x@Wh_top + bh
    // with x = emb[fnode[fmess]] (never materialized)
    gemm1<true, false><<<ggrid, 256, G1_SMEM_BYTES>>>(
        nullptr, 0, Wr, bUr, r1, HID, fmess, fnode, emb,
        nullptr, nullptr, nullptr);
    gemm1<true, false><<<ggrid, 256, G1_SMEM_BYTES>>>(
        nullptr, 0, Wz, bz, xWz, HID, fmess, fnode, emb,
        nullptr, nullptr, nullptr);
    gemm1<true, false><<<ggrid, 256, G1_SMEM_BYTES>>>(
        nullptr, 0, Wh, bh, xWh, HID, fmess, fnode, emb,
        nullptr, nullptr, nullptr);

    // GRU iteration 1 (h = 0): pure elementwise, writes hcat slot 0
    iter1_kernel<<<(int)(((size_t)NMSG * (HID / 4) + 255) / 256), 256>>>(xWz, xWh, hcat);

    // GRU iterations 2..10
    for (int t = 2; t <= 10; t++) {
        // hUr = h@Ur -> hcat slot 1 ; hUz = h@Uz -> hcat slot 2
        gemm1<false, false><<<ggrid, 256, G1_SMEM_BYTES>>>(
            hcat, HCAT, Ur, nullptr, hcat + 256, HCAT,
            nullptr, nullptr, nullptr, nullptr, nullptr, nullptr);
        gemm1<false, false><<<ggrid, 256, G1_SMEM_BYTES>>>(
            hcat, HCAT, Uz, nullptr, hcat + 512, HCAT,
            nullptr, nullptr, nullptr, nullptr, nullptr, nullptr);
        // sg, a=(1-z)sum_h, z
        gather3<<<nblk_msg, 256>>>(hcat, r1, xWz, mess_graph, sg, a, z);
        // h = a + z * tanh(xWh + sg@Uh), row 0 -> 0
        float* hout  = (t == 10) ? messages : hcat;
        int    ldout = (t == 10) ? HID : HCAT;
        gemm1<false, true><<<ggrid, 256, G1_SMEM_BYTES>>>(
            sg, HID, Uh, nullptr, hout, ldout,
            nullptr, nullptr, nullptr, a, z, xWh);
    }

    // Tree vectors from roots only
    epilogue_kernel<<<NTREE, 256>>>(root_indices, fnode, node_graph,
                                    emb, messages, Wo, bo, tree_vecs);

    (void)in_sizes; (void)n_in; (void)out_size;
}